// round 6
// baseline (speedup 1.0000x reference)
#include <cuda_runtime.h>
#include <cstdint>

#define S_LEN 2048
#define B_SZ  32
#define I_DIM 256
#define H_DIM 512

#define NCLUSTERS    16
#define CRANKS       8
#define ROWS_PER_CTA 64
#define REC_THREADS  512

#define CHUNK_F   68                      // 64 data + 4 pad floats (bank-spread)
#define BATCH_B   (8 * CHUNK_F * 4)       // 2176 B per (parity,batch) th image
#define BUF_B     (2 * BATCH_B)           // 4352 B per parity

// ---------------- PTX helpers ----------------
__device__ __forceinline__ uint32_t smem_u32(const void* p) {
    uint32_t a;
    asm("{ .reg .u64 t; cvta.to.shared.u64 t, %1; cvt.u32.u64 %0, t; }" : "=r"(a) : "l"(p));
    return a;
}
__device__ __forceinline__ uint32_t mapa_cluster(uint32_t addr, uint32_t rank) {
    uint32_t r;
    asm("mapa.shared::cluster.u32 %0, %1, %2;" : "=r"(r) : "r"(addr), "r"(rank));
    return r;
}
__device__ __forceinline__ void mbar_init(uint32_t mbar, uint32_t cnt) {
    asm volatile("mbarrier.init.shared.b64 [%0], %1;" :: "r"(mbar), "r"(cnt) : "memory");
}
__device__ __forceinline__ void mbar_expect_tx(uint32_t mbar, uint32_t bytes) {
    asm volatile("mbarrier.arrive.expect_tx.shared.b64 _, [%0], %1;" :: "r"(mbar), "r"(bytes) : "memory");
}
__device__ __forceinline__ void mbar_wait(uint32_t mbar, uint32_t phase) {
    uint32_t done = 0;
    while (!done) {
        asm volatile(
            "{\n\t.reg .pred p;\n\t"
            "mbarrier.try_wait.parity.acquire.cluster.shared::cta.b64 p, [%1], %2, 0x989680;\n\t"
            "selp.b32 %0, 1, 0, p;\n\t}"
            : "=r"(done) : "r"(mbar), "r"(phase) : "memory");
    }
}
__device__ __forceinline__ void st_async_b64(uint32_t daddr, unsigned long long v, uint32_t mbar) {
    asm volatile("st.async.shared::cluster.mbarrier::complete_tx::bytes.b64 [%0], %1, [%2];"
                 :: "r"(daddr), "l"(v), "r"(mbar) : "memory");
}
__device__ __forceinline__ unsigned long long ffma2(unsigned long long a, unsigned long long b,
                                                    unsigned long long c) {
    unsigned long long d;
    asm("fma.rn.f32x2 %0, %1, %2, %3;" : "=l"(d) : "l"(a), "l"(b), "l"(c));
    return d;
}
__device__ __forceinline__ float fold2(unsigned long long v) {
    union { unsigned long long u; float2 f; } c; c.u = v;
    return c.f.x + c.f.y;
}
__device__ __forceinline__ unsigned long long pack2(float x, float y) {
    unsigned long long r;
    asm("mov.b64 %0, {%1, %2};" : "=l"(r) : "r"(__float_as_uint(x)), "r"(__float_as_uint(y)));
    return r;
}
__device__ __forceinline__ float fast_tanh(float h) {
    float hc = fminf(fmaxf(h, -15.f), 15.f);
    float e2 = __expf(2.f * hc);
    return __fdividef(e2 - 1.f, e2 + 1.f);
}
__device__ __forceinline__ void cluster_sync() {
    asm volatile("barrier.cluster.arrive.aligned;\n\tbarrier.cluster.wait.aligned;" ::: "memory");
}

// ---------------- xproj GEMM (R3-proven): out[m,n] = sum_k x[m,k] * Wx[n,k] ----------------
#define BM 128
#define BN 128
#define BK 16

__global__ void __launch_bounds__(256, 2)
xproj_kernel(const float* __restrict__ x,
             const float* __restrict__ Wx,
             float* __restrict__ out)
{
    __shared__ float As[BK][BM];
    __shared__ float Bs[BK][BN];
    const int tid = threadIdx.x;
    const int m0 = blockIdx.y * BM;
    const int n0 = blockIdx.x * BN;
    const int tx = tid & 15;
    const int ty = tid >> 4;

    float acc[8][8];
#pragma unroll
    for (int i = 0; i < 8; i++)
#pragma unroll
        for (int j = 0; j < 8; j++) acc[i][j] = 0.f;

    const float* Aptr = x  + (size_t)m0 * I_DIM;
    const float* Bptr = Wx + (size_t)n0 * I_DIM;

    for (int k0 = 0; k0 < I_DIM; k0 += BK) {
#pragma unroll
        for (int l = 0; l < 2; l++) {
            int idx = tid + l * 256;
            int r   = idx >> 2;
            int c4  = (idx & 3) * 4;
            float4 a = *(const float4*)(Aptr + (size_t)r * I_DIM + k0 + c4);
            As[c4 + 0][r] = a.x; As[c4 + 1][r] = a.y;
            As[c4 + 2][r] = a.z; As[c4 + 3][r] = a.w;
            float4 b = *(const float4*)(Bptr + (size_t)r * I_DIM + k0 + c4);
            Bs[c4 + 0][r] = b.x; Bs[c4 + 1][r] = b.y;
            Bs[c4 + 2][r] = b.z; Bs[c4 + 3][r] = b.w;
        }
        __syncthreads();
#pragma unroll
        for (int kk = 0; kk < BK; kk++) {
            float ra[8], rb[8];
            float4 ra0 = *(const float4*)&As[kk][ty * 8];
            float4 ra1 = *(const float4*)&As[kk][ty * 8 + 4];
            ra[0]=ra0.x; ra[1]=ra0.y; ra[2]=ra0.z; ra[3]=ra0.w;
            ra[4]=ra1.x; ra[5]=ra1.y; ra[6]=ra1.z; ra[7]=ra1.w;
            float4 rb0 = *(const float4*)&Bs[kk][tx * 8];
            float4 rb1 = *(const float4*)&Bs[kk][tx * 8 + 4];
            rb[0]=rb0.x; rb[1]=rb0.y; rb[2]=rb0.z; rb[3]=rb0.w;
            rb[4]=rb1.x; rb[5]=rb1.y; rb[6]=rb1.z; rb[7]=rb1.w;
#pragma unroll
            for (int i = 0; i < 8; i++)
#pragma unroll
                for (int j = 0; j < 8; j++)
                    acc[i][j] += ra[i] * rb[j];
        }
        __syncthreads();
    }

#pragma unroll
    for (int i = 0; i < 8; i++) {
        float* o = out + (size_t)(m0 + ty * 8 + i) * H_DIM + n0 + tx * 8;
        *(float4*)o       = make_float4(acc[i][0], acc[i][1], acc[i][2], acc[i][3]);
        *(float4*)(o + 4) = make_float4(acc[i][4], acc[i][5], acc[i][6], acc[i][7]);
    }
}

// ---------------- recurrence ----------------
// 16 clusters x 8 CTAs; cluster c: batches (2c, 2c+1). CTA rank r: rows
// [r*64, r*64+64). Warp w owns rows 4w..4w+3; lane l: row 4w+(l>>3),
// k-octant q=l&7 (64 k). Per step: mbar wait -> conflict-free LDS.128 of th
// (both batches) -> 64 FFMA2 -> 6 shfl reduce -> owner lanes (l%8==0) update
// h (xp prefetched 1 step ahead), tanh -> 4 pack shfls -> lanes 0,16 send
// b64 row-pairs to 8 peers (st.async) -> STG.64 h. No __syncthreads in loop.
struct RecSmem {
    float th[2][2][8][CHUNK_F];      // [parity][batch][chunk][slot]  17408 B
    unsigned long long mbar[2];
};

__global__ void __cluster_dims__(CRANKS, 1, 1) __launch_bounds__(REC_THREADS, 1)
rec_kernel(const float* __restrict__ Wh,
           const float* __restrict__ tau,
           const float* __restrict__ bias,
           float* __restrict__ out)
{
    __shared__ __align__(16) RecSmem sm;

    const int cid  = blockIdx.x / CRANKS;
    const int rank = blockIdx.x % CRANKS;
    const int t    = threadIdx.x;
    const int w    = t >> 5;
    const int l    = t & 31;
    const int q    = l & 7;                       // k-octant
    const int j    = 4 * w + (l >> 3);            // local row
    const int hg   = rank * ROWS_PER_CTA + j;     // global row

    // weights: row hg, k in [64q, 64q+64) as 32 f32x2 regs
    unsigned long long wreg[32];
    {
        const ulonglong2* wp = (const ulonglong2*)(Wh + (size_t)hg * H_DIM + 64 * q);
#pragma unroll
        for (int i = 0; i < 16; i++) {
            ulonglong2 v = wp[i];
            wreg[2*i]   = v.x;
            wreg[2*i+1] = v.y;
        }
    }

    const uint32_t th_base   = smem_u32(&sm.th[0][0][0][0]);
    const uint32_t mbar_base = smem_u32(&sm.mbar[0]);
    const uint32_t mbar_rel  = mbar_base - th_base;

    uint32_t peer_th[CRANKS];
#pragma unroll
    for (int r = 0; r < CRANKS; r++) peer_th[r] = mapa_cluster(th_base, r);

    if (t == 0) {
        mbar_init(mbar_base,     1);  mbar_expect_tx(mbar_base,     4096);
        mbar_init(mbar_base + 8, 1);  mbar_expect_tx(mbar_base + 8, 4096);
    }
    __syncthreads();
    cluster_sync();   // peers' mbars live before any st.async

    // owner-lane state (l % 8 == 0)
    const bool owner  = (q == 0);
    const bool sender = (l == 0) || (l == 16);
    float* outp0 = out + (size_t)(cid * 2 + 0) * S_LEN * H_DIM + hg;
    float* outp1 = out + (size_t)(cid * 2 + 1) * S_LEN * H_DIM + hg;
    float inv_tau = 1.f, bias_r = 0.f;
    float h0 = 0.f, h1 = 0.f;
    float xc0 = 0.f, xc1 = 0.f;                   // xp for current step
    if (owner) {
        inv_tau = 1.0f / tau[hg];
        bias_r  = bias[hg];
    }
    // dest byte offset of this sender's row pair within a (parity,batch) image
    const uint32_t dstoff = (uint32_t)((hg >> 6) * (CHUNK_F * 4) + (hg & 63) * 4);

#define SEND_PAIR(POFF, PK)                                                    \
    {                                                                          \
        uint32_t _d = (POFF) + dstoff;                                         \
        _Pragma("unroll")                                                      \
        for (int _r = 0; _r < CRANKS; _r++)                                    \
            st_async_b64(peer_th[_r] + _d, (PK),                               \
                         peer_th[_r] + mbar_rel + ((POFF) >= BUF_B ? 8u : 0u));\
    }

    // ---- step 0: v = 0 ----
    if (owner) {
        xc0 = outp0[0];
        xc1 = outp1[0];
        h0 = (xc0 + bias_r) * inv_tau;
        h1 = (xc1 + bias_r) * inv_tau;
    }
    {
        float t0 = owner ? fast_tanh(h0) : 0.f;
        float t1 = owner ? fast_tanh(h1) : 0.f;
        float p0 = __shfl_xor_sync(0xffffffffu, t0, 8);
        float p1 = __shfl_xor_sync(0xffffffffu, t1, 8);
        float q0 = __shfl_xor_sync(0xffffffffu, h0, 8);
        float q1 = __shfl_xor_sync(0xffffffffu, h1, 8);
        if (sender) {
            SEND_PAIR(BUF_B + 0 * BATCH_B, pack2(t0, p0))      // parity 1, batch 0
            SEND_PAIR(BUF_B + 1 * BATCH_B, pack2(t1, p1))      // parity 1, batch 1
            *(float2*)outp0 = make_float2(h0, q0);
            *(float2*)outp1 = make_float2(h1, q1);
        }
    }
    // prefetch xp for step 1
    if (owner) {
        xc0 = outp0[(size_t)1 * H_DIM];
        xc1 = outp1[(size_t)1 * H_DIM];
    }

    uint32_t ph0 = 0, ph1 = 0;

#define STEP_BODY(STEP, P, PH, LAST)                                           \
    {                                                                          \
        float xn0 = 0.f, xn1 = 0.f;                                            \
        if (owner && !(LAST)) {                                                \
            xn0 = outp0[(size_t)((STEP) + 1) * H_DIM];                         \
            xn1 = outp1[(size_t)((STEP) + 1) * H_DIM];                         \
        }                                                                      \
        mbar_wait(mbar_base + (P) * 8, (PH));                                  \
        if (t == 0) mbar_expect_tx(mbar_base + (P) * 8, 4096);                 \
        const ulonglong2* tb0 = (const ulonglong2*)&sm.th[(P)][0][q][0];       \
        const ulonglong2* tb1 = (const ulonglong2*)&sm.th[(P)][1][q][0];       \
        unsigned long long a0e = 0, a0o = 0, a1e = 0, a1o = 0;                 \
        _Pragma("unroll")                                                      \
        for (int i = 0; i < 16; i++) {                                         \
            ulonglong2 c0 = tb0[i];                                            \
            ulonglong2 c1 = tb1[i];                                            \
            a0e = ffma2(wreg[2*i],   c0.x, a0e);                               \
            a0o = ffma2(wreg[2*i+1], c0.y, a0o);                               \
            a1e = ffma2(wreg[2*i],   c1.x, a1e);                               \
            a1o = ffma2(wreg[2*i+1], c1.y, a1o);                               \
        }                                                                      \
        float s0 = fold2(a0e) + fold2(a0o);                                    \
        float s1 = fold2(a1e) + fold2(a1o);                                    \
        s0 += __shfl_xor_sync(0xffffffffu, s0, 1);                             \
        s1 += __shfl_xor_sync(0xffffffffu, s1, 1);                             \
        s0 += __shfl_xor_sync(0xffffffffu, s0, 2);                             \
        s1 += __shfl_xor_sync(0xffffffffu, s1, 2);                             \
        s0 += __shfl_xor_sync(0xffffffffu, s0, 4);                             \
        s1 += __shfl_xor_sync(0xffffffffu, s1, 4);                             \
        float t0 = 0.f, t1 = 0.f;                                              \
        if (owner) {                                                           \
            h0 += (xc0 - h0 + s0 + bias_r) * inv_tau;                          \
            h1 += (xc1 - h1 + s1 + bias_r) * inv_tau;                          \
            t0 = fast_tanh(h0);                                                \
            t1 = fast_tanh(h1);                                                \
        }                                                                      \
        float p0 = __shfl_xor_sync(0xffffffffu, t0, 8);                        \
        float p1 = __shfl_xor_sync(0xffffffffu, t1, 8);                        \
        float q0 = __shfl_xor_sync(0xffffffffu, h0, 8);                        \
        float q1 = __shfl_xor_sync(0xffffffffu, h1, 8);                        \
        if (sender) {                                                          \
            if (!(LAST)) {                                                     \
                SEND_PAIR(((P) ^ 1) * BUF_B + 0 * BATCH_B, pack2(t0, p0))      \
                SEND_PAIR(((P) ^ 1) * BUF_B + 1 * BATCH_B, pack2(t1, p1))      \
            }                                                                  \
            *(float2*)(outp0 + (size_t)(STEP) * H_DIM) = make_float2(h0, q0);  \
            *(float2*)(outp1 + (size_t)(STEP) * H_DIM) = make_float2(h1, q1);  \
        }                                                                      \
        xc0 = xn0; xc1 = xn1;                                                  \
        (PH) ^= 1;                                                             \
    }

    for (int s = 1; s < S_LEN - 1; s += 2) {
        STEP_BODY(s,     1, ph1, 0)
        STEP_BODY(s + 1, 0, ph0, 0)
    }
    STEP_BODY(S_LEN - 1, 1, ph1, 1)
#undef STEP_BODY
#undef SEND_PAIR

    cluster_sync();   // no CTA exits while peers' st.async may target its smem
}

extern "C" void kernel_launch(void* const* d_in, const int* in_sizes, int n_in,
                              void* d_out, int out_size)
{
    const float* x    = (const float*)d_in[0];
    const float* Wx   = (const float*)d_in[1];
    const float* Wh   = (const float*)d_in[2];
    const float* tau  = (const float*)d_in[3];
    const float* bias = (const float*)d_in[4];
    float* out = (float*)d_out;

    dim3 g1(H_DIM / BN, (B_SZ * S_LEN) / BM);
    xproj_kernel<<<g1, 256>>>(x, Wx, out);

    rec_kernel<<<NCLUSTERS * CRANKS, REC_THREADS>>>(Wh, tau, bias, out);
}

// round 7
// speedup vs baseline: 2.0754x; 2.0754x over previous
#include <cuda_runtime.h>
#include <cstdint>

#define S_LEN 2048
#define B_SZ  32
#define I_DIM 256
#define H_DIM 512

#define NCLUSTERS    16
#define CRANKS       8
#define ROWS_PER_CTA 64
#define REC_THREADS  512

// ---------------- PTX helpers ----------------
__device__ __forceinline__ uint32_t smem_u32(const void* p) {
    uint32_t a;
    asm("{ .reg .u64 t; cvta.to.shared.u64 t, %1; cvt.u32.u64 %0, t; }" : "=r"(a) : "l"(p));
    return a;
}
__device__ __forceinline__ uint32_t mapa_cluster(uint32_t addr, uint32_t rank) {
    uint32_t r;
    asm("mapa.shared::cluster.u32 %0, %1, %2;" : "=r"(r) : "r"(addr), "r"(rank));
    return r;
}
__device__ __forceinline__ void mbar_init(uint32_t mbar, uint32_t cnt) {
    asm volatile("mbarrier.init.shared.b64 [%0], %1;" :: "r"(mbar), "r"(cnt) : "memory");
}
__device__ __forceinline__ void mbar_expect_tx(uint32_t mbar, uint32_t bytes) {
    asm volatile("mbarrier.arrive.expect_tx.shared.b64 _, [%0], %1;" :: "r"(mbar), "r"(bytes) : "memory");
}
__device__ __forceinline__ void mbar_wait(uint32_t mbar, uint32_t phase) {
    uint32_t done = 0;
    while (!done) {
        asm volatile(
            "{\n\t.reg .pred p;\n\t"
            "mbarrier.try_wait.parity.acquire.cluster.shared::cta.b64 p, [%1], %2, 0x989680;\n\t"
            "selp.b32 %0, 1, 0, p;\n\t}"
            : "=r"(done) : "r"(mbar), "r"(phase) : "memory");
    }
}
__device__ __forceinline__ void st_async_b64(uint32_t daddr, unsigned long long v, uint32_t mbar) {
    asm volatile("st.async.shared::cluster.mbarrier::complete_tx::bytes.b64 [%0], %1, [%2];"
                 :: "r"(daddr), "l"(v), "r"(mbar) : "memory");
}
__device__ __forceinline__ unsigned long long ffma2(unsigned long long a, unsigned long long b,
                                                    unsigned long long c) {
    unsigned long long d;
    asm("fma.rn.f32x2 %0, %1, %2, %3;" : "=l"(d) : "l"(a), "l"(b), "l"(c));
    return d;
}
__device__ __forceinline__ float fold2(unsigned long long v) {
    union { unsigned long long u; float2 f; } c; c.u = v;
    return c.f.x + c.f.y;
}
__device__ __forceinline__ unsigned long long pack2(float x, float y) {
    unsigned long long r;
    asm("mov.b64 %0, {%1, %2};" : "=l"(r) : "r"(__float_as_uint(x)), "r"(__float_as_uint(y)));
    return r;
}
__device__ __forceinline__ float fast_tanh(float h) {
    float hc = fminf(fmaxf(h, -15.f), 15.f);
    float e2 = __expf(2.f * hc);
    return __fdividef(e2 - 1.f, e2 + 1.f);
}
__device__ __forceinline__ void cluster_sync() {
    asm volatile("barrier.cluster.arrive.aligned;\n\tbarrier.cluster.wait.aligned;" ::: "memory");
}

// ---------------- xproj GEMM (R3-proven): out[m,n] = sum_k x[m,k] * Wx[n,k] ----------------
#define BM 128
#define BN 128
#define BK 16

__global__ void __launch_bounds__(256, 2)
xproj_kernel(const float* __restrict__ x,
             const float* __restrict__ Wx,
             float* __restrict__ out)
{
    __shared__ float As[BK][BM];
    __shared__ float Bs[BK][BN];
    const int tid = threadIdx.x;
    const int m0 = blockIdx.y * BM;
    const int n0 = blockIdx.x * BN;
    const int tx = tid & 15;
    const int ty = tid >> 4;

    float acc[8][8];
#pragma unroll
    for (int i = 0; i < 8; i++)
#pragma unroll
        for (int j = 0; j < 8; j++) acc[i][j] = 0.f;

    const float* Aptr = x  + (size_t)m0 * I_DIM;
    const float* Bptr = Wx + (size_t)n0 * I_DIM;

    for (int k0 = 0; k0 < I_DIM; k0 += BK) {
#pragma unroll
        for (int l = 0; l < 2; l++) {
            int idx = tid + l * 256;
            int r   = idx >> 2;
            int c4  = (idx & 3) * 4;
            float4 a = *(const float4*)(Aptr + (size_t)r * I_DIM + k0 + c4);
            As[c4 + 0][r] = a.x; As[c4 + 1][r] = a.y;
            As[c4 + 2][r] = a.z; As[c4 + 3][r] = a.w;
            float4 b = *(const float4*)(Bptr + (size_t)r * I_DIM + k0 + c4);
            Bs[c4 + 0][r] = b.x; Bs[c4 + 1][r] = b.y;
            Bs[c4 + 2][r] = b.z; Bs[c4 + 3][r] = b.w;
        }
        __syncthreads();
#pragma unroll
        for (int kk = 0; kk < BK; kk++) {
            float ra[8], rb[8];
            float4 ra0 = *(const float4*)&As[kk][ty * 8];
            float4 ra1 = *(const float4*)&As[kk][ty * 8 + 4];
            ra[0]=ra0.x; ra[1]=ra0.y; ra[2]=ra0.z; ra[3]=ra0.w;
            ra[4]=ra1.x; ra[5]=ra1.y; ra[6]=ra1.z; ra[7]=ra1.w;
            float4 rb0 = *(const float4*)&Bs[kk][tx * 8];
            float4 rb1 = *(const float4*)&Bs[kk][tx * 8 + 4];
            rb[0]=rb0.x; rb[1]=rb0.y; rb[2]=rb0.z; rb[3]=rb0.w;
            rb[4]=rb1.x; rb[5]=rb1.y; rb[6]=rb1.z; rb[7]=rb1.w;
#pragma unroll
            for (int i = 0; i < 8; i++)
#pragma unroll
                for (int j = 0; j < 8; j++)
                    acc[i][j] += ra[i] * rb[j];
        }
        __syncthreads();
    }

#pragma unroll
    for (int i = 0; i < 8; i++) {
        float* o = out + (size_t)(m0 + ty * 8 + i) * H_DIM + n0 + tx * 8;
        *(float4*)o       = make_float4(acc[i][0], acc[i][1], acc[i][2], acc[i][3]);
        *(float4*)(o + 4) = make_float4(acc[i][4], acc[i][5], acc[i][6], acc[i][7]);
    }
}

// ---------------- recurrence (R3 skeleton + b64 paired sends + cf reduce + deep prefetch) ----
// 16 clusters x 8 CTAs; cluster c: batches (2c, 2c+1). CTA rank r: rows
// [r*64, r*64+64), Wh slice in registers (f32x2 pairs). Per step: mbar wait ->
// broadcast-LDS GEMV (warp kb covers k-chunk kb*32; rows 2jp,2jp+1; both
// batches) -> partials stored at part[kb][owner_tid] (conflict-free reads) ->
// __syncthreads -> tail t<128 reduces part[w][t], updates h, tanh -> shfl pair
// exchange -> even lane sends b64 to peers 0-3, odd lane to peers 4-7.
struct RecSmem {
    float th[2][2][H_DIM];     // [buf][batch][k]  8KB  (st.async dest)
    float part[16][128];       // partials, column = owner tid
    unsigned long long mbar[2];
};

__global__ void __cluster_dims__(CRANKS, 1, 1) __launch_bounds__(REC_THREADS, 1)
rec_kernel(const float* __restrict__ Wh,
           const float* __restrict__ tau,
           const float* __restrict__ bias,
           float* __restrict__ out)
{
    __shared__ __align__(16) RecSmem sm;

    const int cid  = blockIdx.x / CRANKS;
    const int rank = blockIdx.x % CRANKS;
    const int t    = threadIdx.x;
    const int jp   = t & 31;
    const int kb   = t >> 5;
    const int j0   = 2 * jp;

    // Wh slice in registers (rows j0, j0+1; k in [kb*32, kb*32+32))
    unsigned long long wp0[16], wp1[16];
    {
        const ulonglong2* r0 = (const ulonglong2*)(Wh + (size_t)(rank * ROWS_PER_CTA + j0)     * H_DIM + kb * 32);
        const ulonglong2* r1 = (const ulonglong2*)(Wh + (size_t)(rank * ROWS_PER_CTA + j0 + 1) * H_DIM + kb * 32);
#pragma unroll
        for (int i = 0; i < 8; i++) {
            ulonglong2 a = r0[i]; wp0[2*i] = a.x; wp0[2*i+1] = a.y;
            ulonglong2 b = r1[i]; wp1[2*i] = b.x; wp1[2*i+1] = b.y;
        }
    }

    const uint32_t th_base   = smem_u32(&sm.th[0][0][0]);
    const uint32_t mbar_base = smem_u32(&sm.mbar[0]);
    const uint32_t mbar_rel  = mbar_base - th_base;

    uint32_t peer_th[CRANKS];
#pragma unroll
    for (int r = 0; r < CRANKS; r++) peer_th[r] = mapa_cluster(th_base, r);

    if (t == 0) {
        mbar_init(mbar_base,     1);  mbar_expect_tx(mbar_base,     4096);
        mbar_init(mbar_base + 8, 1);  mbar_expect_tx(mbar_base + 8, 4096);
    }
    __syncthreads();
    cluster_sync();   // peers' mbars live before any st.async

    // tail state (t < 128): one (batch, row) output per thread
    const int bb = t >> 6;
    const int j  = t & 63;
    const int hg = rank * ROWS_PER_CTA + j;
    const int b  = cid * 2 + bb;
    float* outp = out + (size_t)b * S_LEN * H_DIM + hg;

    float h = 0.f, inv_tau = 1.f, bias_r = 0.f, xc = 0.f;
    if (t < 128) {
        inv_tau = 1.0f / tau[hg];
        bias_r  = bias[hg];
    }
    // b64 destination offset: even-row base of this thread's pair
    const uint32_t send_off = (uint32_t)(bb * H_DIM + (hg & ~1)) * 4u;
    const int peer0 = (t & 1) * 4;   // even lane: peers 0-3, odd: peers 4-7

    // ---- step 0: v = 0 ----
    if (t < 128) {
        xc = outp[0];
        h = (xc + bias_r) * inv_tau;
        float thv = fast_tanh(h);
        float tho = __shfl_xor_sync(0xffffffffu, thv, 1);
        float ho  = __shfl_xor_sync(0xffffffffu, h,   1);
        if (!(t & 1)) *(float2*)outp = make_float2(h, ho);
        unsigned long long pk = (t & 1) ? pack2(tho, thv) : pack2(thv, tho);
        uint32_t d = (uint32_t)(2 * H_DIM * 4) + send_off;    // parity-1 buffer
        uint32_t m = mbar_rel + 8u;
#pragma unroll
        for (int rr = 0; rr < 4; rr++)
            st_async_b64(peer_th[peer0 + rr] + d, pk, peer_th[peer0 + rr] + m);
        xc = outp[(size_t)1 * H_DIM];                         // prefetch step 1
    }

    uint32_t ph0 = 0, ph1 = 0;

#define STEP_BODY(STEP, P, PH, LAST)                                               \
    {                                                                              \
        float xn = 0.f;                                                            \
        if (t < 128 && !(LAST)) xn = outp[(size_t)((STEP) + 1) * H_DIM];           \
        mbar_wait(mbar_base + (P) * 8, (PH));                                      \
        if (t == 0) mbar_expect_tx(mbar_base + (P) * 8, 4096);                     \
        const ulonglong2* t0 = (const ulonglong2*)&sm.th[(P)][0][kb * 32];         \
        const ulonglong2* t1 = (const ulonglong2*)&sm.th[(P)][1][kb * 32];         \
        unsigned long long a00 = 0ull, a01 = 0ull, a10 = 0ull, a11 = 0ull;         \
        _Pragma("unroll")                                                          \
        for (int i = 0; i < 8; i++) {                                              \
            ulonglong2 U = t0[i];                                                  \
            ulonglong2 V = t1[i];                                                  \
            a00 = ffma2(wp0[2*i],   U.x, a00);                                     \
            a00 = ffma2(wp0[2*i+1], U.y, a00);                                     \
            a01 = ffma2(wp1[2*i],   U.x, a01);                                     \
            a01 = ffma2(wp1[2*i+1], U.y, a01);                                     \
            a10 = ffma2(wp0[2*i],   V.x, a10);                                     \
            a10 = ffma2(wp0[2*i+1], V.y, a10);                                     \
            a11 = ffma2(wp1[2*i],   V.x, a11);                                     \
            a11 = ffma2(wp1[2*i+1], V.y, a11);                                     \
        }                                                                          \
        *(float2*)&sm.part[kb][j0]      = make_float2(fold2(a00), fold2(a01));     \
        *(float2*)&sm.part[kb][64 + j0] = make_float2(fold2(a10), fold2(a11));     \
        __syncthreads();                                                           \
        if (t < 128) {                                                             \
            float v = 0.f;                                                         \
            _Pragma("unroll")                                                      \
            for (int w = 0; w < 16; w++) v += sm.part[w][t];                       \
            h = h + (xc - h + v + bias_r) * inv_tau;                               \
            float thv = fast_tanh(h);                                              \
            float tho = __shfl_xor_sync(0xffffffffu, thv, 1);                      \
            float ho  = __shfl_xor_sync(0xffffffffu, h,   1);                      \
            if (!(t & 1))                                                          \
                *(float2*)(outp + (size_t)(STEP) * H_DIM) = make_float2(h, ho);    \
            if (!(LAST)) {                                                         \
                unsigned long long pk = (t & 1) ? pack2(tho, thv)                  \
                                                : pack2(thv, tho);                 \
                uint32_t d = (uint32_t)(((P) ^ 1) * 2 * H_DIM * 4) + send_off;     \
                uint32_t m = mbar_rel + (((P) ^ 1) * 8u);                          \
                _Pragma("unroll")                                                  \
                for (int rr = 0; rr < 4; rr++)                                     \
                    st_async_b64(peer_th[peer0 + rr] + d, pk,                      \
                                 peer_th[peer0 + rr] + m);                         \
            }                                                                      \
        }                                                                          \
        xc = xn;                                                                   \
        (PH) ^= 1;                                                                 \
    }

    for (int s = 1; s < S_LEN - 1; s += 2) {
        STEP_BODY(s,     1, ph1, 0)
        STEP_BODY(s + 1, 0, ph0, 0)
    }
    STEP_BODY(S_LEN - 1, 1, ph1, 1)
#undef STEP_BODY

    cluster_sync();   // no CTA exits while peers' st.async may target its smem
}

extern "C" void kernel_launch(void* const* d_in, const int* in_sizes, int n_in,
                              void* d_out, int out_size)
{
    const float* x    = (const float*)d_in[0];
    const float* Wx   = (const float*)d_in[1];
    const float* Wh   = (const float*)d_in[2];
    const float* tau  = (const float*)d_in[3];
    const float* bias = (const float*)d_in[4];
    float* out = (float*)d_out;

    dim3 g1(H_DIM / BN, (B_SZ * S_LEN) / BM);
    xproj_kernel<<<g1, 256>>>(x, Wx, out);

    rec_kernel<<<NCLUSTERS * CRANKS, REC_THREADS>>>(Wh, tau, bias, out);
}